// round 2
// baseline (speedup 1.0000x reference)
#include <cuda_runtime.h>

// ---------------------------------------------------------------------------
// Net_VIF: 6 chained quadrilinear (4D) LUT interpolations, fully fused.
// Numerics replicate the JAX reference's rounding EXACTLY:
//   - per-corner weight = ((w0*w1)*w2)*w3, sequential rn multiplies
//   - corner accumulation order c=0..15 with bit k of c -> dim k
//   - term = v*w then out += term as separate rn mul / rn add (no FMA)
// This matters because the 6-stage chain chaotically amplifies any rounding
// difference by ~16x per stage.
//
// Layout: prepass transposes each LUT from [C, 17^4] to [17^4, float4] in a
// __device__ global so each corner is one 16B load.
// ---------------------------------------------------------------------------

#define LUT_D   17
#define LUT_D2  (LUT_D * LUT_D)
#define LUT_D3  (LUT_D * LUT_D * LUT_D)
#define LUT_D4  (LUT_D * LUT_D * LUT_D * LUT_D)   // 83521
#define N_LUTS  6

// 6 * 83521 * 16 B = ~8 MB static device scratch (allocation-free).
__device__ float4 g_lut[N_LUTS][LUT_D4];

__global__ void lut_transpose_kernel(const float* __restrict__ src, int C, int which) {
    int i = blockIdx.x * blockDim.x + threadIdx.x;
    if (i >= LUT_D4) return;
    float4 v;
    v.x = src[i];
    v.y = src[LUT_D4 + i];
    v.z = src[2 * LUT_D4 + i];
    v.w = (C == 4) ? src[3 * LUT_D4 + i] : 0.0f;
    g_lut[which][i] = v;
}

__device__ __forceinline__ float4 quad_interp4(const float4* __restrict__ lut, float4 x) {
    // clip to [0,1], scale to [0,16]  (x16 is exact; frac is Sterbenz-exact)
    float t0 = __saturatef(x.x) * 16.0f;
    float t1 = __saturatef(x.y) * 16.0f;
    float t2 = __saturatef(x.z) * 16.0f;
    float t3 = __saturatef(x.w) * 16.0f;
    int i0 = min((int)t0, LUT_D - 2);
    int i1 = min((int)t1, LUT_D - 2);
    int i2 = min((int)t2, LUT_D - 2);
    int i3 = min((int)t3, LUT_D - 2);
    float f0 = t0 - (float)i0;
    float f1 = t1 - (float)i1;
    float f2 = t2 - (float)i2;
    float f3 = t3 - (float)i3;
    float g0 = 1.0f - f0, g1 = 1.0f - f1, g2 = 1.0f - f2, g3 = 1.0f - f3;

    // Sequential products matching reference order: ((w0*w1)*w2)*w3.
    // p01[b1*2+b0] = rn(w0*w1); p012[b2*4+..] = rn(p01*w2); w = rn(p012*w3).
    float p01[4];
    p01[0] = __fmul_rn(g0, g1);
    p01[1] = __fmul_rn(f0, g1);
    p01[2] = __fmul_rn(g0, f1);
    p01[3] = __fmul_rn(f0, f1);
    float p012[8];
#pragma unroll
    for (int j = 0; j < 4; ++j) {
        p012[j]     = __fmul_rn(p01[j], g2);
        p012[4 + j] = __fmul_rn(p01[j], f2);
    }
    float w[16];
#pragma unroll
    for (int j = 0; j < 8; ++j) {
        w[j]     = __fmul_rn(p012[j], g3);
        w[8 + j] = __fmul_rn(p012[j], f3);
    }

    const float4* p = lut + (((i0 * LUT_D + i1) * LUT_D + i2) * LUT_D + i3);

    // Fetch all 16 corners (maximize MLP), then accumulate in reference
    // corner order: bit k of c -> dim k (dim0 has stride 17^3).
    float4 v[16];
#pragma unroll
    for (int c = 0; c < 16; ++c) {
        int b0 = c & 1;
        int b1 = (c >> 1) & 1;
        int b2 = (c >> 2) & 1;
        int b3 = (c >> 3) & 1;
        v[c] = __ldg(p + (b0 * LUT_D3 + b1 * LUT_D2 + b2 * LUT_D + b3));
    }

    float4 acc = make_float4(0.0f, 0.0f, 0.0f, 0.0f);
#pragma unroll
    for (int c = 0; c < 16; ++c) {
        // separate rn mul + rn add (no FMA) to match XLA elementwise ops
        float ww = w[((c & 1) * 1) | (((c >> 1) & 1) * 2) |
                     (((c >> 2) & 1) * 4) | (((c >> 3) & 1) * 8)];
        // note: w[] was built with b0 fastest in index -> index == c directly,
        // but keep explicit mapping for clarity; it folds at compile time.
        acc.x = __fadd_rn(acc.x, __fmul_rn(v[c].x, ww));
        acc.y = __fadd_rn(acc.y, __fmul_rn(v[c].y, ww));
        acc.z = __fadd_rn(acc.z, __fmul_rn(v[c].z, ww));
        acc.w = __fadd_rn(acc.w, __fmul_rn(v[c].w, ww));
    }
    return acc;
}

__global__ void net_vif_kernel(const float* __restrict__ vi,
                               const float* __restrict__ ir,
                               float* __restrict__ out) {
    const int HW = 512 * 512;                 // 1<<18
    int p  = blockIdx.x * blockDim.x + threadIdx.x;
    int hw = p & (HW - 1);
    int b  = p >> 18;

    const float* vb = vi + (size_t)b * 3 * HW + hw;
    float4 x;
    x.x = vb[0];
    x.y = vb[HW];
    x.z = vb[2 * HW];
    x.w = ir[(size_t)b * HW + hw];

    x = quad_interp4(g_lut[0], x);   // lut8   (clips input internally)
    x = quad_interp4(g_lut[1], x);   // lut00
    x = quad_interp4(g_lut[2], x);   // lut01
    x = quad_interp4(g_lut[3], x);   // lut02
    x = quad_interp4(g_lut[4], x);   // lut03
    x = quad_interp4(g_lut[5], x);   // lutpgf (final, no clip)

    float* ob = out + (size_t)b * 3 * HW + hw;
    ob[0]      = x.x;
    ob[HW]     = x.y;
    ob[2 * HW] = x.z;
}

extern "C" void kernel_launch(void* const* d_in, const int* in_sizes, int n_in,
                              void* d_out, int out_size) {
    const float* vi = (const float*)d_in[0];   // [8,3,512,512]
    const float* ir = (const float*)d_in[1];   // [8,1,512,512]
    // d_in[2..6] = lut8, lut00, lut01, lut02, lut03 (4ch); d_in[7] = lutpgf (3ch)

    const int tb = 256;
    const int tgrid = (LUT_D4 + tb - 1) / tb;
    for (int k = 0; k < 5; ++k) {
        lut_transpose_kernel<<<tgrid, tb>>>((const float*)d_in[2 + k], 4, k);
    }
    lut_transpose_kernel<<<tgrid, tb>>>((const float*)d_in[7], 3, 5);

    const int total = 8 * 512 * 512;           // 2,097,152
    net_vif_kernel<<<total / 256, 256>>>(vi, ir, (float*)d_out);
}

// round 3
// speedup vs baseline: 1.4823x; 1.4823x over previous
#include <cuda_runtime.h>

// ---------------------------------------------------------------------------
// Net_VIF: 6 chained quadrilinear (4D) LUT interpolations, fully fused,
// bit-exact vs the JAX reference (sequential rn ops, corner order c=0..15).
//
// R3: lane-cooperative corner fetch. LUTs repacked to a 32B-aligned PAIR
// layout so the two b3-adjacent corners of one pixel are fetched by a lane
// PAIR in one LDG round -> each LDG.128's 32 lanes touch 16 cache lines
// instead of 32, halving L1tex wavefront traffic (the measured bottleneck
// class). Values are exchanged with shfl_xor; accumulation order and
// rounding are unchanged (bit movement only).
// ---------------------------------------------------------------------------

#define D   17
#define D2  289
#define D3  4913
#define D4  83521
#define N_LUTS 6

// pair layout: entry e = pair_index*2 + b3 ; pair_index = ((i0*D+i1)*D+i2)*D+i3
// 6 * 83521 * 2 * 16B = ~16 MB static device scratch (allocation-free).
__device__ __align__(128) float4 g_lutP[N_LUTS][D4 * 2];

// Single merged prepass (1 launch): blockIdx.y selects the LUT.
__global__ void lut_pack_kernel(const float* __restrict__ s0, const float* __restrict__ s1,
                                const float* __restrict__ s2, const float* __restrict__ s3,
                                const float* __restrict__ s4, const float* __restrict__ s5) {
    int i = blockIdx.x * blockDim.x + threadIdx.x;
    if (i >= D4) return;
    int which = blockIdx.y;
    const float* src = (which == 0) ? s0 : (which == 1) ? s1 : (which == 2) ? s2
                     : (which == 3) ? s3 : (which == 4) ? s4 : s5;
    bool c4 = (which != 5);
    float4 a;
    a.x = src[i];
    a.y = src[D4 + i];
    a.z = src[2 * D4 + i];
    a.w = c4 ? src[3 * D4 + i] : 0.0f;
    float4 b = make_float4(0.0f, 0.0f, 0.0f, 0.0f);
    if ((i % D) < D - 1) {
        b.x = src[i + 1];
        b.y = src[D4 + i + 1];
        b.z = src[2 * D4 + i + 1];
        b.w = c4 ? src[3 * D4 + i + 1] : 0.0f;
    }
    g_lutP[which][2 * i]     = a;
    g_lutP[which][2 * i + 1] = b;
}

__device__ __forceinline__ int pair_base(float4 xs) {
    float t0 = __saturatef(xs.x) * 16.0f;
    float t1 = __saturatef(xs.y) * 16.0f;
    float t2 = __saturatef(xs.z) * 16.0f;
    float t3 = __saturatef(xs.w) * 16.0f;
    int i0 = min((int)t0, D - 2);
    int i1 = min((int)t1, D - 2);
    int i2 = min((int)t2, D - 2);
    int i3 = min((int)t3, D - 2);
    return ((i0 * D + i1) * D + i2) * D + i3;
}

// Compile-time corner offset within the pair-index space (b3 excluded).
__device__ __forceinline__ int corner_off(int j) {
    return (j & 1) * D3 + ((j >> 1) & 1) * D2 + ((j >> 2) & 1) * D;
}

// One LUT stage for the whole warp (32 pixels), cooperative fetch.
//  Round A: lane l loads pixel (l & ~1) with b3 = (l & 1).
//  Round B: lane l loads pixel (l | 1)  with b3 = 1 - (l & 1).
// => every lane's OWN loads are the b3=0 half of its OWN pixel; the b3=1
//    half arrives from the partner lane via one shfl_xor per float.
__device__ __forceinline__ float4 coop_stage(const float4* __restrict__ lut,
                                             float4 x, int lane) {
    const unsigned FULL = 0xffffffffu;
    const int half = lane & 1;
    const int srcA = lane & ~1;
    const int srcB = lane | 1;

    // Served pixels' inputs (bitwise copies of the owners' x).
    float4 xa, xb;
    xa.x = __shfl_sync(FULL, x.x, srcA);
    xa.y = __shfl_sync(FULL, x.y, srcA);
    xa.z = __shfl_sync(FULL, x.z, srcA);
    xa.w = __shfl_sync(FULL, x.w, srcA);
    xb.x = __shfl_sync(FULL, x.x, srcB);
    xb.y = __shfl_sync(FULL, x.y, srcB);
    xb.z = __shfl_sync(FULL, x.z, srcB);
    xb.w = __shfl_sync(FULL, x.w, srcB);

    const int baseA = pair_base(xa);
    const int baseB = pair_base(xb);
    const int b3A = half;        // round A b3 for this lane
    const int b3B = 1 - half;    // round B b3 for this lane

    // Issue all 16 loads (adjacent lanes of a pair hit the same 128B line).
    float4 vA[8], vB[8];
#pragma unroll
    for (int j = 0; j < 8; ++j)
        vA[j] = __ldg(lut + ((baseA + corner_off(j)) * 2 + b3A));
#pragma unroll
    for (int j = 0; j < 8; ++j)
        vB[j] = __ldg(lut + ((baseB + corner_off(j)) * 2 + b3B));

    // Weights from OWN x, in the reference's exact rounding order:
    // w[c] = ((w0*w1)*w2)*w3 with sequential rn multiplies.
    float t0 = __saturatef(x.x) * 16.0f;
    float t1 = __saturatef(x.y) * 16.0f;
    float t2 = __saturatef(x.z) * 16.0f;
    float t3 = __saturatef(x.w) * 16.0f;
    int i0 = min((int)t0, D - 2);
    int i1 = min((int)t1, D - 2);
    int i2 = min((int)t2, D - 2);
    int i3 = min((int)t3, D - 2);
    float f0 = t0 - (float)i0;
    float f1 = t1 - (float)i1;
    float f2 = t2 - (float)i2;
    float f3 = t3 - (float)i3;
    float g0 = 1.0f - f0, g1 = 1.0f - f1, g2 = 1.0f - f2, g3 = 1.0f - f3;

    float p01[4];
    p01[0] = __fmul_rn(g0, g1);
    p01[1] = __fmul_rn(f0, g1);
    p01[2] = __fmul_rn(g0, f1);
    p01[3] = __fmul_rn(f0, f1);
    float p012[8];
#pragma unroll
    for (int j = 0; j < 4; ++j) {
        p012[j]     = __fmul_rn(p01[j], g2);
        p012[4 + j] = __fmul_rn(p01[j], f2);
    }
    float w0[8], w1[8];
#pragma unroll
    for (int j = 0; j < 8; ++j) {
        w0[j] = __fmul_rn(p012[j], g3);   // corners c = j      (b3 = 0)
        w1[j] = __fmul_rn(p012[j], f3);   // corners c = 8 + j  (b3 = 1)
    }

    // Accumulate c = 0..7 from OWN loads (even lanes: vA; odd lanes: vB).
    float4 acc = make_float4(0.0f, 0.0f, 0.0f, 0.0f);
#pragma unroll
    for (int j = 0; j < 8; ++j) {
        float ox = half ? vB[j].x : vA[j].x;
        float oy = half ? vB[j].y : vA[j].y;
        float oz = half ? vB[j].z : vA[j].z;
        float ow = half ? vB[j].w : vA[j].w;
        acc.x = __fadd_rn(acc.x, __fmul_rn(ox, w0[j]));
        acc.y = __fadd_rn(acc.y, __fmul_rn(oy, w0[j]));
        acc.z = __fadd_rn(acc.z, __fmul_rn(oz, w0[j]));
        acc.w = __fadd_rn(acc.w, __fmul_rn(ow, w0[j]));
    }

    // Exchange: each lane sends the half its partner owns, receives its own
    // pixel's b3=1 corners; accumulate c = 8..15 in order.
#pragma unroll
    for (int j = 0; j < 8; ++j) {
        float sx = half ? vA[j].x : vB[j].x;
        float sy = half ? vA[j].y : vB[j].y;
        float sz = half ? vA[j].z : vB[j].z;
        float sw = half ? vA[j].w : vB[j].w;
        float rx = __shfl_xor_sync(FULL, sx, 1);
        float ry = __shfl_xor_sync(FULL, sy, 1);
        float rz = __shfl_xor_sync(FULL, sz, 1);
        float rw = __shfl_xor_sync(FULL, sw, 1);
        acc.x = __fadd_rn(acc.x, __fmul_rn(rx, w1[j]));
        acc.y = __fadd_rn(acc.y, __fmul_rn(ry, w1[j]));
        acc.z = __fadd_rn(acc.z, __fmul_rn(rz, w1[j]));
        acc.w = __fadd_rn(acc.w, __fmul_rn(rw, w1[j]));
    }
    return acc;
}

__global__ void __launch_bounds__(256, 2)
net_vif_kernel(const float* __restrict__ vi,
               const float* __restrict__ ir,
               float* __restrict__ out) {
    const int HW = 512 * 512;                  // 1<<18
    int p  = blockIdx.x * blockDim.x + threadIdx.x;
    int hw = p & (HW - 1);
    int b  = p >> 18;
    int lane = threadIdx.x & 31;

    const float* vb = vi + (size_t)b * 3 * HW + hw;
    float4 x;
    x.x = vb[0];
    x.y = vb[HW];
    x.z = vb[2 * HW];
    x.w = ir[(size_t)b * HW + hw];

    x = coop_stage(g_lutP[0], x, lane);   // lut8
    x = coop_stage(g_lutP[1], x, lane);   // lut00
    x = coop_stage(g_lutP[2], x, lane);   // lut01
    x = coop_stage(g_lutP[3], x, lane);   // lut02
    x = coop_stage(g_lutP[4], x, lane);   // lut03
    x = coop_stage(g_lutP[5], x, lane);   // lutpgf (no final clip)

    float* ob = out + (size_t)b * 3 * HW + hw;
    ob[0]      = x.x;
    ob[HW]     = x.y;
    ob[2 * HW] = x.z;
}

extern "C" void kernel_launch(void* const* d_in, const int* in_sizes, int n_in,
                              void* d_out, int out_size) {
    const float* vi = (const float*)d_in[0];   // [8,3,512,512]
    const float* ir = (const float*)d_in[1];   // [8,1,512,512]

    dim3 pg((D4 + 255) / 256, N_LUTS);
    lut_pack_kernel<<<pg, 256>>>((const float*)d_in[2], (const float*)d_in[3],
                                 (const float*)d_in[4], (const float*)d_in[5],
                                 (const float*)d_in[6], (const float*)d_in[7]);

    const int total = 8 * 512 * 512;           // 2,097,152
    net_vif_kernel<<<total / 256, 256>>>(vi, ir, (float*)d_out);
}